// round 14
// baseline (speedup 1.0000x reference)
#include <cuda_runtime.h>

#define BB 8192
#define CC 45
#define LL 21
#define EE 22
#define LOG2E 1.4426950408889634f
#define NBLK 1024          // gating blocks (8 batches each)
#define AB 4               // attn batches per block

// ---------------- scratch (__device__ globals, allowed) ----------------
__device__ float g_gate[BB * CC];
__device__ float g_partialT[CC * NBLK];   // transposed: [ch][blk] for coalesced reduce
__device__ int   g_sel[EE];
__device__ float4 g_scal[EE];   // {a*log2e, cm*log2e, alpha, beta}

// conv weights: warp-uniform access -> constant/uniform datapath (off the LSU)
__constant__ float c_gcw[441];
__constant__ float c_gcb[21];

__device__ __forceinline__ float ex2f(float v) {
    float r; asm("ex2.approx.f32 %0, %1;" : "=f"(r) : "f"(v)); return r;
}
__device__ __forceinline__ float rcpf(float v) {
    float r; asm("rcp.approx.f32 %0, %1;" : "=f"(r) : "f"(v)); return r;
}

// ---------------- kernel 1: gating, 2 batches per thread, constant weights ----------------
__global__ __launch_bounds__(192, 5) void gating_kernel(
    const float* __restrict__ x,
    const float* __restrict__ w1, const float* __restrict__ b1,
    const float* __restrict__ w2, const float* __restrict__ b2)
{
    __shared__ float s_x[8][945];
    __shared__ float s_w1[1125];
    __shared__ float s_w2[1125];
    __shared__ float s_b1[25];
    __shared__ float s_b2[45];
    __shared__ float s_mx[8][45];    // conv max -> later reused for logits
    __shared__ float s_av[8][48];    // conv avg -> later reused for gate values
    __shared__ float s_h1m[8][25];
    __shared__ float s_h1a[8][25];

    const int tid = threadIdx.x;

    // ---- cooperative loads ----
    {
        const float4* xb = (const float4*)(x + (size_t)blockIdx.x * 8 * 945);
        float4* sx = (float4*)&s_x[0][0];
        #pragma unroll
        for (int i = tid; i < 8 * 945 / 4; i += 192) sx[i] = xb[i];
    }
    for (int i = tid; i < 1125; i += 192) { s_w1[i] = w1[i]; s_w2[i] = w2[i]; }
    if (tid < 25) s_b1[tid] = b1[tid];
    if (tid < 45) s_b2[tid] = b2[tid];
    __syncthreads();

    const int w0 = tid / 45;            // 0..3 (for tid<180)
    const int i  = tid - w0 * 45;
    const bool act = (tid < 180);

    // ---- conv + max/avg pooling: batches (w0, w0+4) per thread ----
    if (act) {
        float xa[21], xb[21];
        const float* xra = &s_x[w0][i * 21];
        const float* xrb = &s_x[w0 + 4][i * 21];
        #pragma unroll
        for (int l = 0; l < 21; l++) { xa[l] = xra[l]; xb[l] = xrb[l]; }

        float mxA = -1e30f, mxB = -1e30f, sA = 0.f, sB = 0.f;
        #pragma unroll 3
        for (int o = 0; o < 21; o++) {
            float accA = c_gcb[o], accB = accA;
            const float* wr = &c_gcw[o * 21];
            #pragma unroll
            for (int l = 0; l < 21; l++) {
                const float wv = wr[l];            // warp-uniform constant load
                accA = fmaf(wv, xa[l], accA);
                accB = fmaf(wv, xb[l], accB);
            }
            mxA = fmaxf(mxA, accA); sA += accA;
            mxB = fmaxf(mxB, accB); sB += accB;
        }
        s_mx[w0][i] = mxA;      s_av[w0][i] = sA * (1.0f / 21.0f);
        s_mx[w0 + 4][i] = mxB;  s_av[w0 + 4][i] = sB * (1.0f / 21.0f);
    }
    __syncthreads();

    // ---- MLP layer 1 (45->25), 2 batches per thread ----
    if (tid < 100) {
        const int p = tid / 25, j = tid - p * 25;  // batches p, p+4
        float amA = s_b1[j], aaA = amA, amB = amA, aaB = amA;
        const float* wr = &s_w1[j * 45];
        #pragma unroll
        for (int k = 0; k < 45; k++) {
            const float wv = wr[k];
            amA = fmaf(wv, s_mx[p][k], amA);
            aaA = fmaf(wv, s_av[p][k], aaA);
            amB = fmaf(wv, s_mx[p + 4][k], amB);
            aaB = fmaf(wv, s_av[p + 4][k], aaB);
        }
        s_h1m[p][j] = tanhf(amA);  s_h1a[p][j] = tanhf(aaA);
        s_h1m[p + 4][j] = tanhf(amB);  s_h1a[p + 4][j] = tanhf(aaB);
    }
    __syncthreads();

    // ---- MLP layer 2 (25->45), logits -> reuse s_mx ----
    if (act) {
        float amA = s_b2[i], aaA = amA, amB = amA, aaB = amA;
        const float* wr = &s_w2[i * 25];
        #pragma unroll
        for (int k = 0; k < 25; k++) {
            const float wv = wr[k];
            amA = fmaf(wv, s_h1m[w0][k], amA);
            aaA = fmaf(wv, s_h1a[w0][k], aaA);
            amB = fmaf(wv, s_h1m[w0 + 4][k], amB);
            aaB = fmaf(wv, s_h1a[w0 + 4][k], aaB);
        }
        s_mx[w0][i] = tanhf(amA) + tanhf(aaA);
        s_mx[w0 + 4][i] = tanhf(amB) + tanhf(aaB);
    }
    __syncthreads();

    // ---- softmax over 45, warp per batch (6 warps cover 8 batches) ----
    {
        const int wid = tid >> 5, lane = tid & 31;
        for (int bb = wid; bb < 8; bb += 6) {
            float v0 = s_mx[bb][lane];
            float v1 = (lane < 13) ? s_mx[bb][lane + 32] : -1e30f;
            float M = fmaxf(v0, v1);
            #pragma unroll
            for (int off = 16; off; off >>= 1)
                M = fmaxf(M, __shfl_xor_sync(0xffffffffu, M, off));
            float e0 = __expf(v0 - M);
            float e1 = (lane < 13) ? __expf(v1 - M) : 0.f;
            float S = e0 + e1;
            #pragma unroll
            for (int off = 16; off; off >>= 1)
                S += __shfl_xor_sync(0xffffffffu, S, off);
            const float inv = 1.0f / S;
            const float g0 = e0 * inv, g1 = e1 * inv;
            s_av[bb][lane] = g0;
            const size_t gb = ((size_t)blockIdx.x * 8 + bb) * 45;
            g_gate[gb + lane] = g0;
            if (lane < 13) { s_av[bb][lane + 32] = g1; g_gate[gb + lane + 32] = g1; }
        }
    }
    __syncthreads();

    // per-block partial sums for the batch mean (transposed layout, deterministic)
    if (tid < 45) {
        float p = 0.f;
        #pragma unroll
        for (int ww = 0; ww < 8; ww++) p += s_av[ww][tid];
        g_partialT[tid * NBLK + blockIdx.x] = p;
    }
}

// ---------------- kernel 2: mean (float4) + rank-based top-22 + expert scalars ----------------
__global__ __launch_bounds__(1024) void meantopk_kernel(
    const float* __restrict__ wq, const float* __restrict__ bq,
    const float* __restrict__ wk, const float* __restrict__ bk,
    const float* __restrict__ wv, const float* __restrict__ bv,
    const float* __restrict__ wo, const float* __restrict__ bo)
{
    __shared__ float s_mean[45];
    __shared__ int   s_flag[45];

    const int tid = threadIdx.x;
    const int wid = tid >> 5, lane = tid & 31;

    // coalesced float4 column reduce of g_partialT[45][1024]: warp per channel
    for (int ch = wid; ch < 45; ch += 32) {
        const float4* col = (const float4*)&g_partialT[ch * NBLK];
        float s = 0.f;
        #pragma unroll
        for (int j = 0; j < NBLK / 4 / 32; j++) {
            const float4 v = col[lane + 32 * j];
            s += (v.x + v.y) + (v.z + v.w);
        }
        #pragma unroll
        for (int off = 16; off; off >>= 1) s += __shfl_xor_sync(0xffffffffu, s, off);
        if (lane == 0) s_mean[ch] = s;   // scale irrelevant for top-k
    }
    __syncthreads();

    // rank selection: selected iff #{better} < 22, stable tie-break on lower index
    if (tid < 45) {
        const float mv = s_mean[tid];
        int cnt = 0;
        #pragma unroll
        for (int c = 0; c < 45; c++) {
            const float oc = s_mean[c];
            cnt += (oc > mv) || (oc == mv && c < tid);
        }
        s_flag[tid] = (cnt < EE);
    }
    __syncthreads();
    if (tid == 0) {
        int p = 0;
        #pragma unroll
        for (int c = 0; c < 45; c++) if (s_flag[c]) g_sel[p++] = c;
    }

    if (tid >= 64 && tid < 64 + EE) {
        const int e = tid - 64;
        float a = 0.f, cm = 0.f, Al = 0.f, Be = bo[e];
        #pragma unroll
        for (int c = 0; c < 21; c++) {
            a  = fmaf(wq[e * 21 + c], wk[e * 21 + c], a);
            cm = fmaf(bq[e * 21 + c], wk[e * 21 + c], cm);
            Al = fmaf(wo[e * 21 + c], wv[e * 21 + c], Al);
            Be = fmaf(wo[e * 21 + c], bv[e * 21 + c], Be);
        }
        g_scal[e] = make_float4(a * LOG2E, cm * LOG2E, Al, Be);
    }
}

// ---------------- kernel 3: collapsed attention, thread-per-(batch,expert) ----------------
// smem holds only the 22 selected rows (s_xe) + A staging; epilogue reads x from gmem.
__global__ __launch_bounds__(128, 9) void attn_kernel(
    const float* __restrict__ x,
    float* __restrict__ outG, float* __restrict__ outA)
{
    __shared__ float s_xe[AB * EE * 21];   // selected rows: [w][e][l]
    __shared__ float s_A[AB * 945];
    __shared__ float4 s_scal[EE];
    __shared__ int   s_sel[EE];

    const int tid = threadIdx.x;
    const size_t b0 = (size_t)blockIdx.x * AB;

    if (tid < EE) { s_sel[tid] = g_sel[tid]; s_scal[tid] = g_scal[tid]; }
    // zero A staging (covers the 23 unselected channels)
    {
        float4* sA4 = (float4*)s_A;
        const float4 z4 = make_float4(0.f, 0.f, 0.f, 0.f);
        #pragma unroll
        for (int i = tid; i < AB * 945 / 4; i += 128) sA4[i] = z4;
    }
    __syncthreads();

    // stage the 88 selected rows (w,e): 21 consecutive floats each
    #pragma unroll
    for (int i = tid; i < AB * EE * 21; i += 128) {
        const int w = i / (EE * 21);
        const int r = i - w * (EE * 21);
        const int e = r / 21;
        const int l = r - e * 21;
        s_xe[i] = x[(b0 + w) * 945 + s_sel[e] * 21 + l];
    }
    __syncthreads();

    // rotate compute warps across SMSPs so MUFU load is balanced chip-wide
    const int wid = tid >> 5, lane = tid & 31;
    const int lw = (wid - (blockIdx.x & 3)) & 3;
    const int t = lw * 32 + lane;

    if (t < AB * EE) {
        const int w = t / EE, e = t - w * EE;
        const int ch = s_sel[e];
        const float4 sc = s_scal[e];

        const float gate_v = g_gate[(b0 + w) * 45 + ch];

        float xr[21];
        const float* xe = &s_xe[(w * EE + e) * 21];
        #pragma unroll
        for (int l = 0; l < 21; l++) xr[l] = xe[l];

        float* Arow = &s_A[w * 945 + ch * 21];
        #pragma unroll
        for (int l = 0; l < 21; l++) {
            const float u = fmaf(sc.x, xr[l], sc.y);   // (a*xl + cm) * log2e
            float num = 0.f, den = 0.f;
            #pragma unroll
            for (int m = 0; m < 21; m++) {
                const float tt = ex2f(u * xr[m]);
                den += tt;
                num = fmaf(tt, xr[m], num);
            }
            const float y = fmaf(sc.z, num * rcpf(den), sc.w);
            Arow[l] = y * gate_v;
        }
    }
    __syncthreads();

    // coalesced float4 epilogue: A from smem, x fresh from gmem, G = x*A
    {
        const float4* xg = (const float4*)(x + b0 * 945);
        float4* Ag = (float4*)(outA + b0 * 945);
        float4* Gg = (float4*)(outG + b0 * 945);
        const float4* sA4 = (const float4*)s_A;
        #pragma unroll
        for (int i = tid; i < AB * 945 / 4; i += 128) {
            const float4 a = sA4[i];
            const float4 xv = xg[i];
            Ag[i] = a;
            Gg[i] = make_float4(a.x * xv.x, a.y * xv.y, a.z * xv.z, a.w * xv.w);
        }
    }
}

// ---------------- launch ----------------
extern "C" void kernel_launch(void* const* d_in, const int* in_sizes, int n_in,
                              void* d_out, int out_size)
{
    const float* x    = (const float*)d_in[0];
    const float* gc_w = (const float*)d_in[1];
    const float* gc_b = (const float*)d_in[2];
    const float* w1   = (const float*)d_in[3];
    const float* b1   = (const float*)d_in[4];
    const float* w2   = (const float*)d_in[5];
    const float* b2   = (const float*)d_in[6];
    const float* wq   = (const float*)d_in[7];
    const float* bq   = (const float*)d_in[8];
    const float* wk   = (const float*)d_in[9];
    const float* bk   = (const float*)d_in[10];
    const float* wv   = (const float*)d_in[11];
    const float* bv   = (const float*)d_in[12];
    const float* wo   = (const float*)d_in[13];
    const float* bo   = (const float*)d_in[14];

    float* G = (float*)d_out;
    float* A = G + (size_t)BB * CC * LL;   // outputs concatenated: G then A_flat

    // conv weights -> constant memory (D2D async copies; graph-capturable)
    cudaMemcpyToSymbolAsync(c_gcw, gc_w, 441 * sizeof(float), 0,
                            cudaMemcpyDeviceToDevice, 0);
    cudaMemcpyToSymbolAsync(c_gcb, gc_b, 21 * sizeof(float), 0,
                            cudaMemcpyDeviceToDevice, 0);

    gating_kernel<<<NBLK, 192>>>(x, w1, b1, w2, b2);
    meantopk_kernel<<<1, 1024>>>(wq, bq, wk, bk, wv, bv, wo, bo);
    attn_kernel<<<BB / AB, 128>>>(x, G, A);
}

// round 15
// speedup vs baseline: 1.1280x; 1.1280x over previous
#include <cuda_runtime.h>

#define BB 8192
#define CC 45
#define LL 21
#define EE 22
#define LOG2E 1.4426950408889634f
#define NBLK 1024          // gating blocks (8 batches each)
#define AB 4               // attn batches per block

// ---------------- scratch (__device__ globals, allowed) ----------------
__device__ float g_gate[BB * CC];
__device__ float g_partialT[CC * NBLK];   // transposed: [ch][blk] for coalesced reduce
__device__ int   g_sel[EE];
__device__ float4 g_scal[EE];   // {a*log2e, cm*log2e, alpha, beta}

// conv weights: warp-uniform access -> constant/uniform datapath (off the LSU)
__constant__ float c_gcw[441];
__constant__ float c_gcb[21];

__device__ __forceinline__ float ex2f(float v) {
    float r; asm("ex2.approx.f32 %0, %1;" : "=f"(r) : "f"(v)); return r;
}
__device__ __forceinline__ float rcpf(float v) {
    float r; asm("rcp.approx.f32 %0, %1;" : "=f"(r) : "f"(v)); return r;
}

// ---------------- kernel 1: gating, 2 batches per thread, constant weights ----------------
__global__ __launch_bounds__(192, 5) void gating_kernel(
    const float* __restrict__ x,
    const float* __restrict__ w1, const float* __restrict__ b1,
    const float* __restrict__ w2, const float* __restrict__ b2)
{
    __shared__ float s_x[8][945];
    __shared__ float s_w1[1125];
    __shared__ float s_w2[1125];
    __shared__ float s_b1[25];
    __shared__ float s_b2[45];
    __shared__ float s_mx[8][45];    // conv max -> later reused for logits
    __shared__ float s_av[8][48];    // conv avg -> later reused for gate values
    __shared__ float s_h1m[8][25];
    __shared__ float s_h1a[8][25];

    const int tid = threadIdx.x;

    // ---- cooperative loads ----
    {
        const float4* xb = (const float4*)(x + (size_t)blockIdx.x * 8 * 945);
        float4* sx = (float4*)&s_x[0][0];
        #pragma unroll
        for (int i = tid; i < 8 * 945 / 4; i += 192) sx[i] = xb[i];
    }
    for (int i = tid; i < 1125; i += 192) { s_w1[i] = w1[i]; s_w2[i] = w2[i]; }
    if (tid < 25) s_b1[tid] = b1[tid];
    if (tid < 45) s_b2[tid] = b2[tid];
    __syncthreads();

    const int w0 = tid / 45;            // 0..3 (for tid<180)
    const int i  = tid - w0 * 45;
    const bool act = (tid < 180);

    // ---- conv + max/avg pooling: batches (w0, w0+4) per thread ----
    if (act) {
        float xa[21], xb[21];
        const float* xra = &s_x[w0][i * 21];
        const float* xrb = &s_x[w0 + 4][i * 21];
        #pragma unroll
        for (int l = 0; l < 21; l++) { xa[l] = xra[l]; xb[l] = xrb[l]; }

        float mxA = -1e30f, mxB = -1e30f, sA = 0.f, sB = 0.f;
        #pragma unroll 3
        for (int o = 0; o < 21; o++) {
            float accA = c_gcb[o], accB = accA;
            const float* wr = &c_gcw[o * 21];
            #pragma unroll
            for (int l = 0; l < 21; l++) {
                const float wv = wr[l];            // warp-uniform constant load
                accA = fmaf(wv, xa[l], accA);
                accB = fmaf(wv, xb[l], accB);
            }
            mxA = fmaxf(mxA, accA); sA += accA;
            mxB = fmaxf(mxB, accB); sB += accB;
        }
        s_mx[w0][i] = mxA;      s_av[w0][i] = sA * (1.0f / 21.0f);
        s_mx[w0 + 4][i] = mxB;  s_av[w0 + 4][i] = sB * (1.0f / 21.0f);
    }
    __syncthreads();

    // ---- MLP layer 1 (45->25), 2 batches per thread ----
    if (tid < 100) {
        const int p = tid / 25, j = tid - p * 25;  // batches p, p+4
        float amA = s_b1[j], aaA = amA, amB = amA, aaB = amA;
        const float* wr = &s_w1[j * 45];
        #pragma unroll
        for (int k = 0; k < 45; k++) {
            const float wv = wr[k];
            amA = fmaf(wv, s_mx[p][k], amA);
            aaA = fmaf(wv, s_av[p][k], aaA);
            amB = fmaf(wv, s_mx[p + 4][k], amB);
            aaB = fmaf(wv, s_av[p + 4][k], aaB);
        }
        s_h1m[p][j] = tanhf(amA);  s_h1a[p][j] = tanhf(aaA);
        s_h1m[p + 4][j] = tanhf(amB);  s_h1a[p + 4][j] = tanhf(aaB);
    }
    __syncthreads();

    // ---- MLP layer 2 (25->45), logits -> reuse s_mx ----
    if (act) {
        float amA = s_b2[i], aaA = amA, amB = amA, aaB = amA;
        const float* wr = &s_w2[i * 25];
        #pragma unroll
        for (int k = 0; k < 25; k++) {
            const float wv = wr[k];
            amA = fmaf(wv, s_h1m[w0][k], amA);
            aaA = fmaf(wv, s_h1a[w0][k], aaA);
            amB = fmaf(wv, s_h1m[w0 + 4][k], amB);
            aaB = fmaf(wv, s_h1a[w0 + 4][k], aaB);
        }
        s_mx[w0][i] = tanhf(amA) + tanhf(aaA);
        s_mx[w0 + 4][i] = tanhf(amB) + tanhf(aaB);
    }
    __syncthreads();

    // ---- softmax over 45, warp per batch (6 warps cover 8 batches) ----
    {
        const int wid = tid >> 5, lane = tid & 31;
        for (int bb = wid; bb < 8; bb += 6) {
            float v0 = s_mx[bb][lane];
            float v1 = (lane < 13) ? s_mx[bb][lane + 32] : -1e30f;
            float M = fmaxf(v0, v1);
            #pragma unroll
            for (int off = 16; off; off >>= 1)
                M = fmaxf(M, __shfl_xor_sync(0xffffffffu, M, off));
            float e0 = __expf(v0 - M);
            float e1 = (lane < 13) ? __expf(v1 - M) : 0.f;
            float S = e0 + e1;
            #pragma unroll
            for (int off = 16; off; off >>= 1)
                S += __shfl_xor_sync(0xffffffffu, S, off);
            const float inv = 1.0f / S;
            const float g0 = e0 * inv, g1 = e1 * inv;
            s_av[bb][lane] = g0;
            const size_t gb = ((size_t)blockIdx.x * 8 + bb) * 45;
            g_gate[gb + lane] = g0;
            if (lane < 13) { s_av[bb][lane + 32] = g1; g_gate[gb + lane + 32] = g1; }
        }
    }
    __syncthreads();

    // per-block partial sums for the batch mean (transposed layout, deterministic)
    if (tid < 45) {
        float p = 0.f;
        #pragma unroll
        for (int ww = 0; ww < 8; ww++) p += s_av[ww][tid];
        g_partialT[tid * NBLK + blockIdx.x] = p;
    }
}

// ---------------- kernel 2: mean (float4) + rank-based top-22 + expert scalars ----------------
__global__ __launch_bounds__(1024) void meantopk_kernel(
    const float* __restrict__ wq, const float* __restrict__ bq,
    const float* __restrict__ wk, const float* __restrict__ bk,
    const float* __restrict__ wv, const float* __restrict__ bv,
    const float* __restrict__ wo, const float* __restrict__ bo)
{
    __shared__ float s_mean[45];
    __shared__ int   s_flag[45];

    const int tid = threadIdx.x;
    const int wid = tid >> 5, lane = tid & 31;

    // coalesced float4 column reduce of g_partialT[45][1024]: warp per channel
    for (int ch = wid; ch < 45; ch += 32) {
        const float4* col = (const float4*)&g_partialT[ch * NBLK];
        float s = 0.f;
        #pragma unroll
        for (int j = 0; j < NBLK / 4 / 32; j++) {
            const float4 v = col[lane + 32 * j];
            s += (v.x + v.y) + (v.z + v.w);
        }
        #pragma unroll
        for (int off = 16; off; off >>= 1) s += __shfl_xor_sync(0xffffffffu, s, off);
        if (lane == 0) s_mean[ch] = s;   // scale irrelevant for top-k
    }
    __syncthreads();

    // rank selection: selected iff #{better} < 22, stable tie-break on lower index
    if (tid < 45) {
        const float mv = s_mean[tid];
        int cnt = 0;
        #pragma unroll
        for (int c = 0; c < 45; c++) {
            const float oc = s_mean[c];
            cnt += (oc > mv) || (oc == mv && c < tid);
        }
        s_flag[tid] = (cnt < EE);
    }
    __syncthreads();
    if (tid == 0) {
        int p = 0;
        #pragma unroll
        for (int c = 0; c < 45; c++) if (s_flag[c]) g_sel[p++] = c;
    }

    if (tid >= 64 && tid < 64 + EE) {
        const int e = tid - 64;
        float a = 0.f, cm = 0.f, Al = 0.f, Be = bo[e];
        #pragma unroll
        for (int c = 0; c < 21; c++) {
            a  = fmaf(wq[e * 21 + c], wk[e * 21 + c], a);
            cm = fmaf(bq[e * 21 + c], wk[e * 21 + c], cm);
            Al = fmaf(wo[e * 21 + c], wv[e * 21 + c], Al);
            Be = fmaf(wo[e * 21 + c], bv[e * 21 + c], Be);
        }
        g_scal[e] = make_float4(a * LOG2E, cm * LOG2E, Al, Be);
    }
}

// ---------------- kernel 3: collapsed attention, thread-per-(batch,expert) ----------------
// Symmetric factorization: t_lm = S_lm * g_m, S_lm = ex2(aL2E*xl*xm) symmetric ->
// walk upper triangle once, update rows l and m together. 252 ex2 vs 441.
__global__ __launch_bounds__(128) void attn_kernel(
    const float* __restrict__ x,
    float* __restrict__ outG, float* __restrict__ outA)
{
    __shared__ float s_x[AB * 945];
    __shared__ float s_A[AB * 945];
    __shared__ float4 s_scal[EE];
    __shared__ int   s_sel[EE];

    const int tid = threadIdx.x;
    const size_t b0 = (size_t)blockIdx.x * AB;

    // stage x + zero A (both float4, fully coalesced)
    {
        const float4* xg = (const float4*)(x + b0 * 945);
        float4* sx4 = (float4*)s_x;
        float4* sA4 = (float4*)s_A;
        const float4 z4 = make_float4(0.f, 0.f, 0.f, 0.f);
        #pragma unroll
        for (int i = tid; i < AB * 945 / 4; i += 128) { sx4[i] = xg[i]; sA4[i] = z4; }
    }
    if (tid < EE) { s_sel[tid] = g_sel[tid]; s_scal[tid] = g_scal[tid]; }
    __syncthreads();

    // rotate compute warps across SMSPs so MUFU load is balanced chip-wide
    const int wid = tid >> 5, lane = tid & 31;
    const int lw = (wid - (blockIdx.x & 3)) & 3;
    const int t = lw * 32 + lane;

    if (t < AB * EE) {
        const int w = t / EE, e = t - w * EE;
        const int ch = s_sel[e];
        const float4 sc = s_scal[e];
        const int base = w * 945 + ch * 21;

        const float gate_v = g_gate[(b0 + w) * 45 + ch];

        float xr[21], g[21], num[21], den[21];
        #pragma unroll
        for (int l = 0; l < 21; l++) {
            xr[l] = s_x[base + l];
            g[l] = ex2f(sc.y * xr[l]);           // exp(cm * x_m)
            num[l] = 0.f; den[l] = 0.f;
        }

        #pragma unroll
        for (int l = 0; l < 21; l++) {
            const float ul = sc.x * xr[l];        // aL2E * xl
            // diagonal
            {
                const float S = ex2f(ul * xr[l]);
                const float t2 = S * g[l];
                den[l] += t2;
                num[l] = fmaf(t2, xr[l], num[l]);
            }
            #pragma unroll
            for (int m = l + 1; m < 21; m++) {
                const float S = ex2f(ul * xr[m]); // symmetric S_lm = S_ml
                const float t2 = S * g[m];
                const float t3 = S * g[l];
                den[l] += t2;
                num[l] = fmaf(t2, xr[m], num[l]);
                den[m] += t3;
                num[m] = fmaf(t3, xr[l], num[m]);
            }
        }

        float* Arow = &s_A[base];
        #pragma unroll
        for (int l = 0; l < 21; l++) {
            const float y = fmaf(sc.z, num[l] * rcpf(den[l]), sc.w);
            Arow[l] = y * gate_v;
        }
    }
    __syncthreads();

    // coalesced float4 write of A and G = x * A (covers zeroed channels too)
    {
        float4* Ag = (float4*)(outA + b0 * 945);
        float4* Gg = (float4*)(outG + b0 * 945);
        const float4* sx4 = (const float4*)s_x;
        const float4* sA4 = (const float4*)s_A;
        #pragma unroll
        for (int i = tid; i < AB * 945 / 4; i += 128) {
            const float4 a = sA4[i];
            const float4 xv = sx4[i];
            Ag[i] = a;
            Gg[i] = make_float4(a.x * xv.x, a.y * xv.y, a.z * xv.z, a.w * xv.w);
        }
    }
}

// ---------------- launch ----------------
extern "C" void kernel_launch(void* const* d_in, const int* in_sizes, int n_in,
                              void* d_out, int out_size)
{
    const float* x    = (const float*)d_in[0];
    const float* gc_w = (const float*)d_in[1];
    const float* gc_b = (const float*)d_in[2];
    const float* w1   = (const float*)d_in[3];
    const float* b1   = (const float*)d_in[4];
    const float* w2   = (const float*)d_in[5];
    const float* b2   = (const float*)d_in[6];
    const float* wq   = (const float*)d_in[7];
    const float* bq   = (const float*)d_in[8];
    const float* wk   = (const float*)d_in[9];
    const float* bk   = (const float*)d_in[10];
    const float* wv   = (const float*)d_in[11];
    const float* bv   = (const float*)d_in[12];
    const float* wo   = (const float*)d_in[13];
    const float* bo   = (const float*)d_in[14];

    float* G = (float*)d_out;
    float* A = G + (size_t)BB * CC * LL;   // outputs concatenated: G then A_flat

    // conv weights -> constant memory (D2D async copies; graph-capturable)
    cudaMemcpyToSymbolAsync(c_gcw, gc_w, 441 * sizeof(float), 0,
                            cudaMemcpyDeviceToDevice, 0);
    cudaMemcpyToSymbolAsync(c_gcb, gc_b, 21 * sizeof(float), 0,
                            cudaMemcpyDeviceToDevice, 0);

    gating_kernel<<<NBLK, 192>>>(x, w1, b1, w2, b2);
    meantopk_kernel<<<1, 1024>>>(wq, bq, wk, bk, wv, bv, wo, bo);
    attn_kernel<<<BB / AB, 128>>>(x, G, A);
}

// round 16
// speedup vs baseline: 1.2878x; 1.1417x over previous
#include <cuda_runtime.h>

#define BB 8192
#define CC 45
#define LL 21
#define EE 22
#define LOG2E 1.4426950408889634f
#define NBLK 1024          // gating blocks (8 batches each)
#define AB 4               // attn batches per block

typedef unsigned long long u64x;

// ---------------- scratch (__device__ globals, allowed) ----------------
__device__ float g_gate[BB * CC];
__device__ float g_partialT[CC * NBLK];   // transposed: [ch][blk] for coalesced reduce
__device__ int   g_sel[EE];
__device__ float4 g_scal[EE];   // {a*log2e, cm*log2e, alpha, beta}

__device__ __forceinline__ float ex2f(float v) {
    float r; asm("ex2.approx.f32 %0, %1;" : "=f"(r) : "f"(v)); return r;
}
__device__ __forceinline__ float rcpf(float v) {
    float r; asm("rcp.approx.f32 %0, %1;" : "=f"(r) : "f"(v)); return r;
}
__device__ __forceinline__ u64x fma2(u64x a, u64x b, u64x c) {
    u64x d; asm("fma.rn.f32x2 %0, %1, %2, %3;" : "=l"(d) : "l"(a), "l"(b), "l"(c)); return d;
}
__device__ __forceinline__ u64x add2(u64x a, u64x b) {
    u64x d; asm("add.rn.f32x2 %0, %1, %2;" : "=l"(d) : "l"(a), "l"(b)); return d;
}
__device__ __forceinline__ u64x pack2(float lo, float hi) {
    u64x d; asm("mov.b64 %0, {%1, %2};" : "=l"(d) : "f"(lo), "f"(hi)); return d;
}
__device__ __forceinline__ void unpack2(u64x v, float& lo, float& hi) {
    asm("mov.b64 {%0, %1}, %2;" : "=f"(lo), "=f"(hi) : "l"(v));
}

// ---------------- kernel 1: gating, 4 batches/thread, f32x2 conv, paired smem weights ---
// block = 128; 8 batches per block; conv threads tid<90: g=tid/45 in {0,1}, i=tid%45,
// handling batches {g, g+2, g+4, g+6} as f32x2 pairs (g,g+4) and (g+2,g+6).
// One LDS.64 broadcast weight feeds 2 FFMA2 = 4 MACs -> LSU and FMA pressure both ~4x down.
__global__ __launch_bounds__(128, 4) void gating_kernel(
    const float* __restrict__ x,
    const float* __restrict__ gc_w, const float* __restrict__ gc_b,
    const float* __restrict__ w1, const float* __restrict__ b1,
    const float* __restrict__ w2, const float* __restrict__ b2)
{
    __shared__ float  s_x[8][945];
    __shared__ __align__(8) float2 s_gcw2[441];   // duplicated (w,w) pairs
    __shared__ __align__(8) float2 s_gcb2[21];
    __shared__ float s_w1[1125];
    __shared__ float s_w2[1125];
    __shared__ float s_b1[25];
    __shared__ float s_b2[45];
    __shared__ float s_mx[8][45];    // conv max -> later reused for logits
    __shared__ float s_av[8][48];    // conv avg -> later reused for gate values
    __shared__ float s_h1m[8][25];
    __shared__ float s_h1a[8][25];

    const int tid = threadIdx.x;

    // ---- cooperative loads ----
    {
        const float4* xb = (const float4*)(x + (size_t)blockIdx.x * 8 * 945);
        float4* sx = (float4*)&s_x[0][0];
        #pragma unroll
        for (int i = tid; i < 8 * 945 / 4; i += 128) sx[i] = xb[i];
    }
    for (int i = tid; i < 441; i += 128) {
        const float v = gc_w[i];
        s_gcw2[i] = make_float2(v, v);
    }
    for (int i = tid; i < 1125; i += 128) { s_w1[i] = w1[i]; s_w2[i] = w2[i]; }
    if (tid < 21) { const float v = gc_b[tid]; s_gcb2[tid] = make_float2(v, v); }
    if (tid < 25) s_b1[tid] = b1[tid];
    if (tid < 45) s_b2[tid] = b2[tid];
    __syncthreads();

    const int g = tid / 45;             // 0..1 (for tid<90)
    const int i = tid - g * 45;
    const bool act = (tid < 90);

    // ---- conv + max/avg pooling: 4 batches packed in 2 f32x2 pairs ----
    if (act) {
        u64x xp0[21], xp1[21];
        {
            const float* r0 = &s_x[g][i * 21];
            const float* r4 = &s_x[g + 4][i * 21];
            const float* r2 = &s_x[g + 2][i * 21];
            const float* r6 = &s_x[g + 6][i * 21];
            #pragma unroll
            for (int l = 0; l < 21; l++) {
                xp0[l] = pack2(r0[l], r4[l]);   // (g, g+4)
                xp1[l] = pack2(r2[l], r6[l]);   // (g+2, g+6)
            }
        }
        float m0 = -1e30f, m2 = -1e30f, m4 = -1e30f, m6 = -1e30f;
        u64x sum0 = 0ULL, sum1 = 0ULL;
        #pragma unroll 3
        for (int o = 0; o < 21; o++) {
            const u64x bias = *(const u64x*)&s_gcb2[o];
            u64x a0 = bias, a1 = bias;
            const u64x* wr = (const u64x*)&s_gcw2[o * 21];
            #pragma unroll
            for (int l = 0; l < 21; l++) {
                const u64x wv = wr[l];          // one LDS.64 broadcast
                a0 = fma2(wv, xp0[l], a0);
                a1 = fma2(wv, xp1[l], a1);
            }
            float f0, f4, f2, f6;
            unpack2(a0, f0, f4);
            unpack2(a1, f2, f6);
            m0 = fmaxf(m0, f0); m4 = fmaxf(m4, f4);
            m2 = fmaxf(m2, f2); m6 = fmaxf(m6, f6);
            sum0 = add2(sum0, a0);
            sum1 = add2(sum1, a1);
        }
        float s0, s4, s2, s6;
        unpack2(sum0, s0, s4);
        unpack2(sum1, s2, s6);
        s_mx[g][i] = m0;      s_av[g][i] = s0 * (1.0f / 21.0f);
        s_mx[g + 2][i] = m2;  s_av[g + 2][i] = s2 * (1.0f / 21.0f);
        s_mx[g + 4][i] = m4;  s_av[g + 4][i] = s4 * (1.0f / 21.0f);
        s_mx[g + 6][i] = m6;  s_av[g + 6][i] = s6 * (1.0f / 21.0f);
    }
    __syncthreads();

    // ---- MLP layer 1 (45->25), 2 batches per thread ----
    if (tid < 100) {
        const int p = tid / 25, j = tid - p * 25;  // batches p, p+4
        float amA = s_b1[j], aaA = amA, amB = amA, aaB = amA;
        const float* wr = &s_w1[j * 45];
        #pragma unroll
        for (int k = 0; k < 45; k++) {
            const float wv = wr[k];
            amA = fmaf(wv, s_mx[p][k], amA);
            aaA = fmaf(wv, s_av[p][k], aaA);
            amB = fmaf(wv, s_mx[p + 4][k], amB);
            aaB = fmaf(wv, s_av[p + 4][k], aaB);
        }
        s_h1m[p][j] = tanhf(amA);  s_h1a[p][j] = tanhf(aaA);
        s_h1m[p + 4][j] = tanhf(amB);  s_h1a[p + 4][j] = tanhf(aaB);
    }
    __syncthreads();

    // ---- MLP layer 2 (25->45), 4 batches per thread, logits -> reuse s_mx ----
    if (act) {
        float am0 = s_b2[i], aa0 = am0, am2 = am0, aa2 = am0;
        float am4 = am0, aa4 = am0, am6 = am0, aa6 = am0;
        const float* wr = &s_w2[i * 25];
        #pragma unroll
        for (int k = 0; k < 25; k++) {
            const float wv = wr[k];
            am0 = fmaf(wv, s_h1m[g][k], am0);      aa0 = fmaf(wv, s_h1a[g][k], aa0);
            am2 = fmaf(wv, s_h1m[g + 2][k], am2);  aa2 = fmaf(wv, s_h1a[g + 2][k], aa2);
            am4 = fmaf(wv, s_h1m[g + 4][k], am4);  aa4 = fmaf(wv, s_h1a[g + 4][k], aa4);
            am6 = fmaf(wv, s_h1m[g + 6][k], am6);  aa6 = fmaf(wv, s_h1a[g + 6][k], aa6);
        }
        s_mx[g][i]     = tanhf(am0) + tanhf(aa0);
        s_mx[g + 2][i] = tanhf(am2) + tanhf(aa2);
        s_mx[g + 4][i] = tanhf(am4) + tanhf(aa4);
        s_mx[g + 6][i] = tanhf(am6) + tanhf(aa6);
    }
    __syncthreads();

    // ---- softmax over 45, warp per batch (4 warps cover 8 batches) ----
    {
        const int wid = tid >> 5, lane = tid & 31;
        for (int bb = wid; bb < 8; bb += 4) {
            float v0 = s_mx[bb][lane];
            float v1 = (lane < 13) ? s_mx[bb][lane + 32] : -1e30f;
            float M = fmaxf(v0, v1);
            #pragma unroll
            for (int off = 16; off; off >>= 1)
                M = fmaxf(M, __shfl_xor_sync(0xffffffffu, M, off));
            float e0 = __expf(v0 - M);
            float e1 = (lane < 13) ? __expf(v1 - M) : 0.f;
            float S = e0 + e1;
            #pragma unroll
            for (int off = 16; off; off >>= 1)
                S += __shfl_xor_sync(0xffffffffu, S, off);
            const float inv = 1.0f / S;
            const float g0 = e0 * inv, g1 = e1 * inv;
            s_av[bb][lane] = g0;
            const size_t gb = ((size_t)blockIdx.x * 8 + bb) * 45;
            g_gate[gb + lane] = g0;
            if (lane < 13) { s_av[bb][lane + 32] = g1; g_gate[gb + lane + 32] = g1; }
        }
    }
    __syncthreads();

    // per-block partial sums for the batch mean (transposed layout, deterministic)
    if (tid < 45) {
        float p = 0.f;
        #pragma unroll
        for (int ww = 0; ww < 8; ww++) p += s_av[ww][tid];
        g_partialT[tid * NBLK + blockIdx.x] = p;
    }
}

// ---------------- kernel 2: mean (float4) + rank-based top-22 + expert scalars ----------------
__global__ __launch_bounds__(1024) void meantopk_kernel(
    const float* __restrict__ wq, const float* __restrict__ bq,
    const float* __restrict__ wk, const float* __restrict__ bk,
    const float* __restrict__ wv, const float* __restrict__ bv,
    const float* __restrict__ wo, const float* __restrict__ bo)
{
    __shared__ float s_mean[45];
    __shared__ int   s_flag[45];

    const int tid = threadIdx.x;
    const int wid = tid >> 5, lane = tid & 31;

    // coalesced float4 column reduce of g_partialT[45][1024]: warp per channel
    for (int ch = wid; ch < 45; ch += 32) {
        const float4* col = (const float4*)&g_partialT[ch * NBLK];
        float s = 0.f;
        #pragma unroll
        for (int j = 0; j < NBLK / 4 / 32; j++) {
            const float4 v = col[lane + 32 * j];
            s += (v.x + v.y) + (v.z + v.w);
        }
        #pragma unroll
        for (int off = 16; off; off >>= 1) s += __shfl_xor_sync(0xffffffffu, s, off);
        if (lane == 0) s_mean[ch] = s;   // scale irrelevant for top-k
    }
    __syncthreads();

    // rank selection: selected iff #{better} < 22, stable tie-break on lower index
    if (tid < 45) {
        const float mv = s_mean[tid];
        int cnt = 0;
        #pragma unroll
        for (int c = 0; c < 45; c++) {
            const float oc = s_mean[c];
            cnt += (oc > mv) || (oc == mv && c < tid);
        }
        s_flag[tid] = (cnt < EE);
    }
    __syncthreads();
    if (tid == 0) {
        int p = 0;
        #pragma unroll
        for (int c = 0; c < 45; c++) if (s_flag[c]) g_sel[p++] = c;
    }

    if (tid >= 64 && tid < 64 + EE) {
        const int e = tid - 64;
        float a = 0.f, cm = 0.f, Al = 0.f, Be = bo[e];
        #pragma unroll
        for (int c = 0; c < 21; c++) {
            a  = fmaf(wq[e * 21 + c], wk[e * 21 + c], a);
            cm = fmaf(bq[e * 21 + c], wk[e * 21 + c], cm);
            Al = fmaf(wo[e * 21 + c], wv[e * 21 + c], Al);
            Be = fmaf(wo[e * 21 + c], bv[e * 21 + c], Be);
        }
        g_scal[e] = make_float4(a * LOG2E, cm * LOG2E, Al, Be);
    }
}

// ---------------- kernel 3: collapsed attention, symmetric triangle + packed (den,num) ----
// t_lm = S_lm * g_m with S symmetric; gh[m] = (g_m, g_m*x_m) packed so each side of the
// pair update is ONE FFMA2: (den,num) += S * (g, h). 3 fma-pipe ops + 1 ex2 per pair.
__global__ __launch_bounds__(128, 3) void attn_kernel(
    const float* __restrict__ x,
    float* __restrict__ outG, float* __restrict__ outA)
{
    __shared__ float s_x[AB * 945];
    __shared__ float s_A[AB * 945];
    __shared__ float4 s_scal[EE];
    __shared__ int   s_sel[EE];

    const int tid = threadIdx.x;
    const size_t b0 = (size_t)blockIdx.x * AB;

    // stage x + zero A (both float4, fully coalesced)
    {
        const float4* xg = (const float4*)(x + b0 * 945);
        float4* sx4 = (float4*)s_x;
        float4* sA4 = (float4*)s_A;
        const float4 z4 = make_float4(0.f, 0.f, 0.f, 0.f);
        #pragma unroll
        for (int i = tid; i < AB * 945 / 4; i += 128) { sx4[i] = xg[i]; sA4[i] = z4; }
    }
    if (tid < EE) { s_sel[tid] = g_sel[tid]; s_scal[tid] = g_scal[tid]; }
    __syncthreads();

    // rotate compute warps across SMSPs so MUFU load is balanced chip-wide
    const int wid = tid >> 5, lane = tid & 31;
    const int lw = (wid - (blockIdx.x & 3)) & 3;
    const int t = lw * 32 + lane;

    if (t < AB * EE) {
        const int w = t / EE, e = t - w * EE;
        const int ch = s_sel[e];
        const float4 sc = s_scal[e];
        const int base = w * 945 + ch * 21;

        const float gate_v = g_gate[(b0 + w) * 45 + ch];

        float xr[21];
        u64x gh[21], dn[21];
        #pragma unroll
        for (int l = 0; l < 21; l++) xr[l] = s_x[base + l];
        #pragma unroll
        for (int l = 0; l < 21; l++) {
            const float gg = ex2f(sc.y * xr[l]);   // exp(cm * x_m)
            gh[l] = pack2(gg, gg * xr[l]);         // (g, h = g*x)
            dn[l] = 0ULL;                          // (den, num) = (0, 0)
        }

        #pragma unroll
        for (int l = 0; l < 21; l++) {
            const float ul = sc.x * xr[l];         // aL2E * xl
            {
                const float S = ex2f(ul * xr[l]);  // diagonal
                dn[l] = fma2(pack2(S, S), gh[l], dn[l]);
            }
            #pragma unroll
            for (int m = l + 1; m < 21; m++) {
                const float S = ex2f(ul * xr[m]);  // symmetric S_lm = S_ml
                const u64x Sp = pack2(S, S);
                dn[l] = fma2(Sp, gh[m], dn[l]);
                dn[m] = fma2(Sp, gh[l], dn[m]);
            }
        }

        float* Arow = &s_A[base];
        #pragma unroll
        for (int l = 0; l < 21; l++) {
            float den, num;
            unpack2(dn[l], den, num);
            const float y = fmaf(sc.z, num * rcpf(den), sc.w);
            Arow[l] = y * gate_v;
        }
    }
    __syncthreads();

    // coalesced float4 write of A and G = x * A (covers zeroed channels too)
    {
        float4* Ag = (float4*)(outA + b0 * 945);
        float4* Gg = (float4*)(outG + b0 * 945);
        const float4* sx4 = (const float4*)s_x;
        const float4* sA4 = (const float4*)s_A;
        #pragma unroll
        for (int i = tid; i < AB * 945 / 4; i += 128) {
            const float4 a = sA4[i];
            const float4 xv = sx4[i];
            Ag[i] = a;
            Gg[i] = make_float4(a.x * xv.x, a.y * xv.y, a.z * xv.z, a.w * xv.w);
        }
    }
}

// ---------------- launch ----------------
extern "C" void kernel_launch(void* const* d_in, const int* in_sizes, int n_in,
                              void* d_out, int out_size)
{
    const float* x    = (const float*)d_in[0];
    const float* gc_w = (const float*)d_in[1];
    const float* gc_b = (const float*)d_in[2];
    const float* w1   = (const float*)d_in[3];
    const float* b1   = (const float*)d_in[4];
    const float* w2   = (const float*)d_in[5];
    const float* b2   = (const float*)d_in[6];
    const float* wq   = (const float*)d_in[7];
    const float* bq   = (const float*)d_in[8];
    const float* wk   = (const float*)d_in[9];
    const float* bk   = (const float*)d_in[10];
    const float* wv   = (const float*)d_in[11];
    const float* bv   = (const float*)d_in[12];
    const float* wo   = (const float*)d_in[13];
    const float* bo   = (const float*)d_in[14];

    float* G = (float*)d_out;
    float* A = G + (size_t)BB * CC * LL;   // outputs concatenated: G then A_flat

    gating_kernel<<<NBLK, 128>>>(x, gc_w, gc_b, w1, b1, w2, b2);
    meantopk_kernel<<<1, 1024>>>(wq, bq, wk, bk, wv, bv, wo, bo);
    attn_kernel<<<BB / AB, 128>>>(x, G, A);
}